// round 16
// baseline (speedup 1.0000x reference)
#include <cuda_runtime.h>
#include <cuda_fp16.h>
#include <math.h>
#include <stdint.h>

// ---------------- problem constants ----------------
#define BB 2
#define TT 2048
#define DD 1024
#define HH 16
#define HD 64
#define NL 6
#define DF 4096
#define NTOK (BB*TT)          // 4096 rows
#define QKVLD 5120            // fused QKVZR row stride
#define EPSLN 1e-5f

// ---------------- device scratch (no allocs allowed) ----------------
__device__ float  g_x   [NTOK*DD];
__device__ __half g_xn  [NTOK*DD];
__device__ __half g_qkvzr[(size_t)NTOK*QKVLD];
__device__ __half g_y   [NTOK*DD];
__device__ __half g_h1  [(size_t)NTOK*DF];

// transposed fp16 weights, K-major [N][K]
__device__ __half g_wtqkvzr[(size_t)NL*QKVLD*DD];
__device__ __half g_wto    [(size_t)NL*DD*DD];
__device__ __half g_wt1    [(size_t)NL*DF*DD];
__device__ __half g_wt2    [(size_t)NL*DD*DF];
__device__ float  g_bcat   [NL*QKVLD];

// ---------------- helpers ----------------
__device__ __forceinline__ float exp2a(float x) {
    float y;
    asm("ex2.approx.f32 %0, %1;" : "=f"(y) : "f"(x));
    return y;
}

__device__ __forceinline__ uint32_t half2_as_u(__half2 h) {
    return *reinterpret_cast<uint32_t*>(&h);
}

__device__ __forceinline__ void mma_f16(float* d, const uint32_t* a, const uint32_t* b) {
    asm volatile(
        "mma.sync.aligned.m16n8k16.row.col.f32.f16.f16.f32 "
        "{%0,%1,%2,%3}, {%4,%5,%6,%7}, {%8,%9}, {%0,%1,%2,%3};"
        : "+f"(d[0]), "+f"(d[1]), "+f"(d[2]), "+f"(d[3])
        : "r"(a[0]), "r"(a[1]), "r"(a[2]), "r"(a[3]),
          "r"(b[0]), "r"(b[1]));
}

#define LDSM4(r0, r1, r2, r3, addr) \
    asm volatile("ldmatrix.sync.aligned.m8n8.x4.shared.b16 {%0,%1,%2,%3}, [%4];" \
                 : "=r"(r0), "=r"(r1), "=r"(r2), "=r"(r3) : "r"(addr))

#define LDSM4T(r0, r1, r2, r3, addr) \
    asm volatile("ldmatrix.sync.aligned.m8n8.x4.trans.shared.b16 {%0,%1,%2,%3}, [%4];" \
                 : "=r"(r0), "=r"(r1), "=r"(r2), "=r"(r3) : "r"(addr))

__device__ __forceinline__ float sigmoidf_(float x) { return 1.0f / (1.0f + expf(-x)); }

__device__ __forceinline__ uint32_t smem_u32(const void* p) {
    uint32_t a;
    asm("{ .reg .u64 t; cvta.to.shared.u64 t, %1; cvt.u32.u64 %0, t; }" : "=r"(a) : "l"(p));
    return a;
}

__device__ __forceinline__ void cp16(uint32_t dst, const void* src) {
    asm volatile("cp.async.cg.shared.global [%0], [%1], 16;" :: "r"(dst), "l"(src) : "memory");
}
#define CP_COMMIT() asm volatile("cp.async.commit_group;" ::: "memory")
#define CP_WAIT(n)  asm volatile("cp.async.wait_group %0;" :: "n"(n) : "memory")

// ---------------- layernorm: one WARP per row, register-resident ----------------
template <typename OutT>
__global__ __launch_bounds__(256) void layernorm_warp_kernel(
        const float* __restrict__ x, const float* __restrict__ w,
        const float* __restrict__ b, OutT* __restrict__ out) {
    const int row  = blockIdx.x * 8 + (threadIdx.x >> 5);
    const int lane = threadIdx.x & 31;
    const float4* xr = (const float4*)(x + (size_t)row * DD);
    const float4* w4 = (const float4*)w;
    const float4* b4 = (const float4*)b;

    float4 v[8];
    float sum = 0.f, ss = 0.f;
    #pragma unroll
    for (int i = 0; i < 8; i++) {
        v[i] = xr[lane + 32 * i];
        sum += v[i].x + v[i].y + v[i].z + v[i].w;
        ss  += v[i].x * v[i].x + v[i].y * v[i].y + v[i].z * v[i].z + v[i].w * v[i].w;
    }
    #pragma unroll
    for (int d = 16; d > 0; d >>= 1) {
        sum += __shfl_xor_sync(0xffffffffu, sum, d);
        ss  += __shfl_xor_sync(0xffffffffu, ss, d);
    }
    const float mu = sum * (1.0f / DD);
    const float var = ss * (1.0f / DD) - mu * mu;
    const float rs = rsqrtf(var + EPSLN);

    #pragma unroll
    for (int i = 0; i < 8; i++) {
        const int c4 = lane + 32 * i;
        float4 wv = w4[c4];
        float4 bv = b4[c4];
        float o0 = (v[i].x - mu) * rs * wv.x + bv.x;
        float o1 = (v[i].y - mu) * rs * wv.y + bv.y;
        float o2 = (v[i].z - mu) * rs * wv.z + bv.z;
        float o3 = (v[i].w - mu) * rs * wv.w + bv.w;
        if (sizeof(OutT) == 2) {
            __half2 h0 = __floats2half2_rn(o0, o1);
            __half2 h1 = __floats2half2_rn(o2, o3);
            uint2 pk = {half2_as_u(h0), half2_as_u(h1)};
            *(uint2*)((__half*)out + (size_t)row * DD + c4 * 4) = pk;
        } else {
            float4 o = {o0, o1, o2, o3};
            *(float4*)((float*)out + (size_t)row * DD + c4 * 4) = o;
        }
    }
}

// ---------------- weight transpose to fp16 (single matrix) ----------------
__global__ __launch_bounds__(256) void transpose_h_kernel(
        const float* __restrict__ src, __half* __restrict__ dst, int K, int N) {
    __shared__ float tile[32][33];
    int k0 = blockIdx.y * 32, n0 = blockIdx.x * 32;
    int tx = threadIdx.x & 31, ty = threadIdx.x >> 5;
    #pragma unroll
    for (int i = 0; i < 4; i++)
        tile[ty + i * 8][tx] = src[(size_t)(k0 + ty + i * 8) * N + n0 + tx];
    __syncthreads();
    #pragma unroll
    for (int i = 0; i < 4; i++)
        dst[(size_t)(n0 + ty + i * 8) * K + k0 + tx] = __float2half(tile[tx][ty + i * 8]);
}

__global__ void biaspack_kernel(const float* __restrict__ bq, const float* __restrict__ bk,
                                const float* __restrict__ bv, const float* __restrict__ bz,
                                const float* __restrict__ br, float* __restrict__ out) {
    int i = blockIdx.x * blockDim.x + threadIdx.x;
    if (i >= NL * QKVLD) return;
    int l = i / QKVLD, j = i % QKVLD;
    int m = j >> 10, c = j & 1023;
    const float* src = (m == 0) ? bq : (m == 1) ? bk : (m == 2) ? bv : (m == 3) ? bz : br;
    out[i] = src[l * 1024 + c];
}

// ---------------- fp16 tensor-core GEMM: BK=32, 4-stage cp.async, ldmatrix ----------------
// epi: 0=bias->out, 1=bias+GELU->out, 2=gate1(x), 3=gate2(x)
#define GBM 128
#define GBN 128
#define GBK 32
#define GP 40
#define GTILE (GBM*GP)
#define GSTAGES 4
#define GEMM_SMEM (2*GSTAGES*GTILE*2)

struct EpiArgs {
    float* xbuf;            // gate modes: x written here
    const __half* qz;       // gate1/gate2: fused qkvzr (z/r logits)
    const float* srcp;      // gate1: residual-x read source; gate2: sequences
};

__global__ __launch_bounds__(256) void gemm_f16_kernel(
        const __half* __restrict__ A, const __half* __restrict__ WT,
        const float* __restrict__ bias, void* __restrict__ Cout,
        int K, int ldC, int epi, int outHalf, EpiArgs ea) {
    extern __shared__ char dynsm[];
    __half* As = (__half*)dynsm;
    __half* Bs = As + GSTAGES * GTILE;

    const int tid  = threadIdx.x;
    const int warp = tid >> 5;
    const int lane = tid & 31;
    const int g    = lane >> 2;
    const int tg   = lane & 3;
    const int row0 = blockIdx.y * GBM;
    const int col0 = blockIdx.x * GBN;
    const int wm   = (warp >> 2) * 64;
    const int wn   = (warp & 3) * 32;

    float acc[4][4][4];
    #pragma unroll
    for (int i = 0; i < 4; i++)
        #pragma unroll
        for (int j = 0; j < 4; j++)
            #pragma unroll
            for (int c = 0; c < 4; c++) acc[i][j][c] = 0.f;

    const __half* Ag = A  + (size_t)row0 * K;
    const __half* Bg = WT + (size_t)col0 * K;
    const uint32_t as_base = smem_u32(As);
    const uint32_t bs_base = smem_u32(Bs);

    const uint32_t a_lane = ((uint32_t)(wm + (lane & 15)) * GP + ((lane >> 4) << 3)) * 2;
    const int bsel = (lane >> 3) & 3;
    const uint32_t b_lane = ((uint32_t)(wn + ((bsel >> 1) << 3) + (lane & 7)) * GP
                            + ((bsel & 1) << 3)) * 2;

    auto issue = [&](int it, int buf) {
        const int k0 = it * GBK;
        uint32_t ad = as_base + buf * (GTILE * 2);
        uint32_t bd = bs_base + buf * (GTILE * 2);
        #pragma unroll
        for (int i = 0; i < 2; i++) {
            int idx = tid + i * 256;
            int r = idx >> 2, seg = (idx & 3) * 8;
            cp16(ad + (r * GP + seg) * 2, Ag + (size_t)r * K + k0 + seg);
            cp16(bd + (r * GP + seg) * 2, Bg + (size_t)r * K + k0 + seg);
        }
    };

    const int nit = K / GBK;
    issue(0, 0); CP_COMMIT();
    if (nit > 1) { issue(1, 1); CP_COMMIT(); }
    if (nit > 2) { issue(2, 2); CP_COMMIT(); }

    for (int it = 0; it < nit; it++) {
        const int buf = it & 3;
        const int pend = ((it + 2 < nit) ? 2 : (it + 1 < nit) ? 1 : 0);
        if (pend == 2) CP_WAIT(2);
        else if (pend == 1) CP_WAIT(1);
        else CP_WAIT(0);
        __syncthreads();
        if (it + 3 < nit) { issue(it + 3, (it + 3) & 3); CP_COMMIT(); }

        const uint32_t ab = as_base + buf * (GTILE * 2) + a_lane;
        const uint32_t bb = bs_base + buf * (GTILE * 2) + b_lane;
        #pragma unroll
        for (int ks = 0; ks < 2; ks++) {
            const uint32_t ko = ks * 32;
            uint32_t af[4][4], bf[4][2];
            #pragma unroll
            for (int fm = 0; fm < 4; fm++)
                LDSM4(af[fm][0], af[fm][1], af[fm][2], af[fm][3],
                      ab + fm * (16 * GP * 2) + ko);
            #pragma unroll
            for (int fnp = 0; fnp < 2; fnp++)
                LDSM4(bf[2 * fnp][0], bf[2 * fnp][1], bf[2 * fnp + 1][0], bf[2 * fnp + 1][1],
                      bb + fnp * (16 * GP * 2) + ko);
            #pragma unroll
            for (int fm = 0; fm < 4; fm++)
                #pragma unroll
                for (int fn = 0; fn < 4; fn++)
                    mma_f16(acc[fm][fn], af[fm], bf[fn]);
        }
    }

    // ---------------- epilogue ----------------
    #pragma unroll
    for (int fm = 0; fm < 4; fm++) {
        int r1 = row0 + wm + fm * 16 + g;
        #pragma unroll
        for (int fn = 0; fn < 4; fn++) {
            int cl = wn + fn * 8 + tg * 2;
            int cg0 = col0 + cl;
            float bz0 = bias[cg0];
            float bz1 = bias[cg0 + 1];
            float v00 = acc[fm][fn][0] + bz0;
            float v01 = acc[fm][fn][1] + bz1;
            float v10 = acc[fm][fn][2] + bz0;
            float v11 = acc[fm][fn][3] + bz1;

            if (epi == 0) {
                if (outHalf) {
                    __half* ch = (__half*)Cout;
                    *(__half2*)(ch + (size_t)r1 * ldC + cg0) = __floats2half2_rn(v00, v01);
                    *(__half2*)(ch + (size_t)(r1 + 8) * ldC + cg0) = __floats2half2_rn(v10, v11);
                } else {
                    float* cf = (float*)Cout;
                    float2 o0 = {v00, v01};
                    float2 o1 = {v10, v11};
                    *(float2*)(cf + (size_t)r1 * ldC + cg0) = o0;
                    *(float2*)(cf + (size_t)(r1 + 8) * ldC + cg0) = o1;
                }
            } else if (epi == 1) {
                v00 = 0.5f * v00 * (1.0f + erff(v00 * 0.70710678118654752440f));
                v01 = 0.5f * v01 * (1.0f + erff(v01 * 0.70710678118654752440f));
                v10 = 0.5f * v10 * (1.0f + erff(v10 * 0.70710678118654752440f));
                v11 = 0.5f * v11 * (1.0f + erff(v11 * 0.70710678118654752440f));
                __half* ch = (__half*)Cout;
                *(__half2*)(ch + (size_t)r1 * ldC + cg0) = __floats2half2_rn(v00, v01);
                *(__half2*)(ch + (size_t)(r1 + 8) * ldC + cg0) = __floats2half2_rn(v10, v11);
            } else if (epi == 2) {
                // gate1: x = (1-z)*xin + z*tanh(r*v)   (xin = ea.srcp; z,r from qkvzr)
                #pragma unroll
                for (int h = 0; h < 2; h++) {
                    int rr = r1 + h * 8;
                    float va = h ? v10 : v00;
                    float vb = h ? v11 : v01;
                    size_t qb_ = (size_t)rr * QKVLD + cg0;
                    __half2 zl = *(const __half2*)(ea.qz + qb_ + 3072);
                    __half2 rl = *(const __half2*)(ea.qz + qb_ + 4096);
                    float2 zf = __half22float2(zl);
                    float2 rf = __half22float2(rl);
                    float z0 = sigmoidf_(zf.x);
                    float z1 = sigmoidf_(zf.y);
                    float rg0 = sigmoidf_(rf.x);
                    float rg1 = sigmoidf_(rf.y);
                    size_t xi = (size_t)rr * DD + cg0;
                    float2 xv = *(const float2*)(ea.srcp + xi);
                    float h0 = tanhf(rg0 * va);
                    float h1v = tanhf(rg1 * vb);
                    float2 xo = {(1.0f - z0) * xv.x + z0 * h0,
                                 (1.0f - z1) * xv.y + z1 * h1v};
                    *(float2*)(ea.xbuf + xi) = xo;
                }
            } else {
                // gate2: x = (1-z)*x + z*v + src   (z recomputed from qkvzr logits)
                #pragma unroll
                for (int h = 0; h < 2; h++) {
                    int rr = r1 + h * 8;
                    float va = h ? v10 : v00;
                    float vb = h ? v11 : v01;
                    size_t qb_ = (size_t)rr * QKVLD + cg0;
                    __half2 zl = *(const __half2*)(ea.qz + qb_ + 3072);
                    float2 zf = __half22float2(zl);
                    float z0 = sigmoidf_(zf.x);
                    float z1 = sigmoidf_(zf.y);
                    size_t xi = (size_t)rr * DD + cg0;
                    float2 xv = *(float2*)(ea.xbuf + xi);
                    float2 sv = *(float2*)(ea.srcp + xi);
                    float2 xo = {(1.0f - z0) * xv.x + z0 * va + sv.x,
                                 (1.0f - z1) * xv.y + z1 * vb + sv.y};
                    *(float2*)(ea.xbuf + xi) = xo;
                }
            }
        }
    }
}

// ---------------- fused causal flash attention (fp16 MMA, reg-P, ldmatrix.trans V) ----------------
#define FBM 128
#define FBN 64
#define FP 72   // pitch in halves
#define FLASH_SMEM ((FBM*FP + 4*FBN*FP) * 2)   // Q + K[2] + V[2] = 55296 B

__global__ __launch_bounds__(256, 2) void flash_attn_kernel(
        const __half* __restrict__ QKV, __half* __restrict__ O) {
    extern __shared__ char dynsm[];
    __half* Qs = (__half*)dynsm;             // [128][FP]
    __half* Ks = Qs + FBM * FP;              // [2][64][FP]
    __half* Vs = Ks + 2 * FBN * FP;          // [2][64][FP] token-major

    const int tx = threadIdx.x;
    const int warp = tx >> 5;
    const int lane = tx & 31;
    const int g  = lane >> 2;
    const int tg = lane & 3;
    const int qb = gridDim.x - 1 - blockIdx.x;
    const int bh = blockIdx.y;
    const int bb = bh >> 4, hh = bh & 15;
    const int qbase = qb * FBM;

    const __half* qptr = QKV + (size_t)bb * TT * QKVLD + hh * HD;
    const __half* kptr = qptr + 1024;
    const __half* vptr = qptr + 2048;

    const uint32_t ks_base = smem_u32(Ks);
    const uint32_t vs_base = smem_u32(Vs);

    #pragma unroll
    for (int i = 0; i < 4; i++) {
        int idx = tx + i * 256;
        int r = idx >> 3, c8 = (idx & 7) * 8;
        *(uint4*)&Qs[r * FP + c8] =
            *(const uint4*)(qptr + (size_t)(qbase + r) * QKVLD + c8);
    }

    float m0 = -1e30f, m1 = -1e30f, l0 = 0.f, l1 = 0.f;
    float o[8][4];
    #pragma unroll
    for (int nt = 0; nt < 8; nt++)
        #pragma unroll
        for (int c = 0; c < 4; c++) o[nt][c] = 0.f;

    const int myrow0 = qbase + warp * 16;
    const float sl2e = 0.125f * 1.44269504088896f;

    auto issueKV = [&](int kb, int buf) {
        #pragma unroll
        for (int i = 0; i < 2; i++) {
            int idx = tx + i * 256;
            int r = idx >> 3, c8 = (idx & 7) * 8;
            size_t gro = (size_t)(kb * FBN + r) * QKVLD + c8;
            uint32_t so = (uint32_t)(buf * (FBN * FP) + r * FP + c8) * 2;
            cp16(ks_base + so, kptr + gro);
            cp16(vs_base + so, vptr + gro);
        }
    };

    const uint32_t vt_lane = (uint32_t)((((lane >> 3) & 1) << 3) + (lane & 7)) * FP
                             + ((lane >> 4) << 3);

    const int kbmax = 2 * qb + 1;
    issueKV(0, 0); CP_COMMIT();

    for (int kb = 0; kb <= kbmax; kb++) {
        const int buf = kb & 1;
        if (kb < kbmax) { issueKV(kb + 1, buf ^ 1); CP_COMMIT(); CP_WAIT(1); }
        else            { CP_WAIT(0); }
        __syncthreads();

        if (kb * FBN <= myrow0 + 15) {
            const __half* Kb = Ks + buf * (FBN * FP);

            float s[8][4];
            #pragma unroll
            for (int nt = 0; nt < 8; nt++)
                #pragma unroll
                for (int c = 0; c < 4; c++) s[nt][c] = 0.f;

            #pragma unroll
            for (int ks = 0; ks < 4; ks++) {
                const int kc = ks * 16;
                uint32_t a[4];
                const __half* p = &Qs[(warp * 16 + g) * FP + kc + 2 * tg];
                a[0] = *(const uint32_t*)p;
                a[1] = *(const uint32_t*)(p + 8 * FP);
                a[2] = *(const uint32_t*)(p + 8);
                a[3] = *(const uint32_t*)(p + 8 * FP + 8);
                #pragma unroll
                for (int nt = 0; nt < 8; nt++) {
                    uint32_t b[2];
                    const __half* q = &Kb[(nt * 8 + g) * FP + kc + 2 * tg];
                    b[0] = *(const uint32_t*)q;
                    b[1] = *(const uint32_t*)(q + 8);
                    mma_f16(s[nt], a, b);
                }
            }

            const int r0 = myrow0 + g, r1 = r0 + 8;
            const bool dm = (kb >= 2 * qb);
            #pragma unroll
            for (int nt = 0; nt < 8; nt++) {
                int c0 = kb * FBN + nt * 8 + 2 * tg;
                s[nt][0] *= sl2e; s[nt][1] *= sl2e;
                s[nt][2] *= sl2e; s[nt][3] *= sl2e;
                if (dm) {
                    if (c0     > r0) s[nt][0] = -1e30f;
                    if (c0 + 1 > r0) s[nt][1] = -1e30f;
                    if (c0     > r1) s[nt][2] = -1e30f;
                    if (c0 + 1 > r1) s[nt][3] = -1e30f;
                }
            }

            float rm0 = -1e30f, rm1 = -1e30f;
            #pragma unroll
            for (int nt = 0; nt < 8; nt++) {
                rm0 = fmaxf(rm0, fmaxf(s[nt][0], s[nt][1]));
                rm1 = fmaxf(rm1, fmaxf(s[nt][2], s[nt][3]));
            }
            rm0 = fmaxf(rm0, __shfl_xor_sync(0xffffffffu, rm0, 1));
            rm0 = fmaxf(rm0, __shfl_xor_sync(0xffffffffu, rm0, 2));
            rm1 = fmaxf(rm1, __shfl_xor_sync(0xffffffffu, rm1, 1));
            rm1 = fmaxf(rm1, __shfl_xor_sync(0xffffffffu, rm1, 2));
            float mn0 = fmaxf(m0, rm0), mn1 = fmaxf(m1, rm1);
            float al0 = exp2a(m0 - mn0), al1 = exp2a(m1 - mn1);
            m0 = mn0; m1 = mn1;

            uint32_t pa[8][2];
            float rs0 = 0.f, rs1 = 0.f;
            #pragma unroll
            for (int nt = 0; nt < 8; nt++) {
                float p0 = exp2a(s[nt][0] - m0);
                float p1 = exp2a(s[nt][1] - m0);
                float p2 = exp2a(s[nt][2] - m1);
                float p3 = exp2a(s[nt][3] - m1);
                rs0 += p0 + p1;
                rs1 += p2 + p3;
                pa[nt][0] = half2_as_u(__floats2half2_rn(p0, p1));
                pa[nt][1] = half2_as_u(__floats2half2_rn(p2, p3));
            }
            rs0 += __shfl_xor_sync(0xffffffffu, rs0, 1);
            rs0 += __shfl_xor_sync(0xffffffffu, rs0, 2);
            rs1 += __shfl_xor_sync(0xffffffffu, rs1, 1);
            rs1 += __shfl_xor_sync(0xffffffffu, rs1, 2);
            l0 = l0 * al0 + rs0;
            l1 = l1 * al1 + rs1;
            #pragma unroll
            for (int nt = 0; nt < 8; nt++) {
                o[nt][0] *= al0; o[nt][1] *= al0;
                o[nt][2] *= al1; o[nt][3] *= al1;
            }

            const uint32_t vb_base = vs_base + (uint32_t)(buf * (FBN * FP) + vt_lane) * 2;
            #pragma unroll
            for (int j = 0; j < 4; j++) {
                uint32_t a[4] = {pa[2 * j][0], pa[2 * j][1],
                                 pa[2 * j + 1][0], pa[2 * j + 1][1]};
                #pragma unroll
                for (int ntp = 0; ntp < 4; ntp++) {
                    uint32_t b0, b1, b2, b3;
                    LDSM4T(b0, b1, b2, b3,
                           vb_base + (uint32_t)(j * 16 * FP + ntp * 16) * 2);
                    uint32_t bA[2] = {b0, b1};
                    uint32_t bB[2] = {b2, b3};
                    mma_f16(o[2 * ntp], a, bA);
                    mma_f16(o[2 * ntp + 1], a, bB);
                }
            }
        }
        __syncthreads();
    }

    float i0 = 1.0f / l0, i1 = 1.0f / l1;
    __half* ob = O + ((size_t)bb * TT + myrow0 + g) * DD + hh * HD;
    #pragma unroll
    for (int nt = 0; nt < 8; nt++) {
        int c = nt * 8 + 2 * tg;
        *(__half2*)(ob + c) = __floats2half2_rn(o[nt][0] * i0, o[nt][1] * i0);
        *(__half2*)(ob + (size_t)8 * DD + c) = __floats2half2_rn(o[nt][2] * i1, o[nt][3] * i1);
    }
}

// ---------------- host orchestration ----------------
static void* symv(const void* s) {
    void* p = nullptr;
    cudaGetSymbolAddress(&p, s);
    return p;
}

extern "C" void kernel_launch(void* const* d_in, const int* in_sizes, int n_in,
                              void* d_out, int out_size) {
    const float* seq  = (const float*)d_in[0];
    const float* Wq   = (const float*)d_in[1];
    const float* bq   = (const float*)d_in[2];
    const float* Wk   = (const float*)d_in[3];
    const float* bk   = (const float*)d_in[4];
    const float* Wv   = (const float*)d_in[5];
    const float* bv   = (const float*)d_in[6];
    const float* Wo   = (const float*)d_in[7];
    const float* bo   = (const float*)d_in[8];
    const float* Wz   = (const float*)d_in[9];
    const float* bz   = (const float*)d_in[10];
    const float* Wr   = (const float*)d_in[11];
    const float* br   = (const float*)d_in[12];
    const float* W1   = (const float*)d_in[13];
    const float* b1   = (const float*)d_in[14];
    const float* W2   = (const float*)d_in[15];
    const float* b2   = (const float*)d_in[16];
    const float* ln1w = (const float*)d_in[17];
    const float* ln1b = (const float*)d_in[18];
    const float* ln2w = (const float*)d_in[19];
    const float* ln2b = (const float*)d_in[20];
    const float* lnfw = (const float*)d_in[21];
    const float* lnfb = (const float*)d_in[22];

    float*  x     = (float*)symv(g_x);
    __half* xn    = (__half*)symv(g_xn);
    __half* qkvzr = (__half*)symv(g_qkvzr);
    __half* y     = (__half*)symv(g_y);
    __half* h1    = (__half*)symv(g_h1);
    __half* wtqkv = (__half*)symv(g_wtqkvzr);
    __half* wto   = (__half*)symv(g_wto);
    __half* wt1   = (__half*)symv(g_wt1);
    __half* wt2   = (__half*)symv(g_wt2);
    float*  bcat  = (float*)symv(g_bcat);

    static bool init_done = false;
    static cudaStream_t s2, s3;
    static cudaEvent_t evRoot, evW5[NL], evL[NL], evLN1[NL], evZR[NL];
    if (!init_done) {
        cudaFuncSetAttribute(flash_attn_kernel,
                             cudaFuncAttributeMaxDynamicSharedMemorySize, FLASH_SMEM);
        cudaFuncSetAttribute(gemm_f16_kernel,
                             cudaFuncAttributeMaxDynamicSharedMemorySize, GEMM_SMEM);
        cudaStreamCreateWithFlags(&s2, cudaStreamNonBlocking);
        cudaStreamCreateWithFlags(&s3, cudaStreamNonBlocking);
        cudaEventCreateWithFlags(&evRoot, cudaEventDisableTiming);
        for (int l = 0; l < NL; l++) {
            cudaEventCreateWithFlags(&evW5[l], cudaEventDisableTiming);
            cudaEventCreateWithFlags(&evL[l], cudaEventDisableTiming);
            cudaEventCreateWithFlags(&evLN1[l], cudaEventDisableTiming);
            cudaEventCreateWithFlags(&evZR[l], cudaEventDisableTiming);
        }
        init_done = true;
    }

    // ---- fork transposes + biaspack onto s2 (R14 event topology) ----
    cudaEventRecord(evRoot, 0);
    cudaStreamWaitEvent(s2, evRoot, 0);
    biaspack_kernel<<<(NL * QKVLD + 255) / 256, 256, 0, s2>>>(bq, bk, bv, bz, br, bcat);
    {
        size_t dsz = (size_t)DD * DD;
        dim3 tD(DD / 32, DD / 32);
        dim3 t1(DF / 32, DD / 32);
        dim3 t2(DD / 32, DF / 32);
        for (int l = 0; l < NL; l++) {
            size_t o5 = (size_t)l * QKVLD * DD;
            transpose_h_kernel<<<tD, 256, 0, s2>>>(Wq + l * dsz, wtqkv + o5 + 0ull * dsz, DD, DD);
            transpose_h_kernel<<<tD, 256, 0, s2>>>(Wk + l * dsz, wtqkv + o5 + 1ull * dsz, DD, DD);
            transpose_h_kernel<<<tD, 256, 0, s2>>>(Wv + l * dsz, wtqkv + o5 + 2ull * dsz, DD, DD);
            transpose_h_kernel<<<tD, 256, 0, s2>>>(Wz + l * dsz, wtqkv + o5 + 3ull * dsz, DD, DD);
            transpose_h_kernel<<<tD, 256, 0, s2>>>(Wr + l * dsz, wtqkv + o5 + 4ull * dsz, DD, DD);
            cudaEventRecord(evW5[l], s2);
            transpose_h_kernel<<<tD, 256, 0, s2>>>(Wo + l * dsz, wto + l * dsz, DD, DD);
            transpose_h_kernel<<<t1, 256, 0, s2>>>(W1 + (size_t)l * DD * DF, wt1 + (size_t)l * DF * DD, DD, DF);
            transpose_h_kernel<<<t2, 256, 0, s2>>>(W2 + (size_t)l * DF * DD, wt2 + (size_t)l * DD * DF, DF, DD);
            cudaEventRecord(evL[l], s2);
        }
    }

    dim3 gQKV(3072 / GBN, NTOK / GBM);     // (24, 32)
    dim3 gZR(2048 / GBN, NTOK / GBM);      // (16, 32)
    dim3 gO(DD / GBN, NTOK / GBM);         // (8, 32)
    dim3 gM1(DF / GBN, NTOK / GBM);        // (32, 32)
    dim3 gFA(TT / FBM, BB * HH);           // (16, 32)
    const int lnBlocks = NTOK / 8;         // 512

    EpiArgs eaNone = {nullptr, nullptr, nullptr};
    const size_t dsz = (size_t)DD * DD;

    for (int l = 0; l < NL; l++) {
        const float* xin = (l == 0) ? seq : x;
        const __half* wl = wtqkv + (size_t)l * QKVLD * DD;

        layernorm_warp_kernel<__half><<<lnBlocks, 256>>>(xin, ln1w + l * DD, ln1b + l * DD, xn);
        cudaEventRecord(evLN1[l], 0);

        // ZR projection on s3 (overlaps flash on main stream)
        cudaStreamWaitEvent(s3, evLN1[l], 0);
        cudaStreamWaitEvent(s3, evW5[l], 0);
        gemm_f16_kernel<<<gZR, 256, GEMM_SMEM, s3>>>(
            xn, wl + 3ull * dsz, bcat + l * QKVLD + 3072, qkvzr + 3072,
            DD, QKVLD, 0, 1, eaNone);
        cudaEventRecord(evZR[l], s3);

        // QKV projection on main stream
        cudaStreamWaitEvent(0, evW5[l], 0);
        gemm_f16_kernel<<<gQKV, 256, GEMM_SMEM>>>(
            xn, wl, bcat + l * QKVLD, qkvzr,
            DD, QKVLD, 0, 1, eaNone);

        flash_attn_kernel<<<gFA, 256, FLASH_SMEM>>>(qkvzr, y);

        // Wo GEMM + fused gate1 (needs z/r from s3 and Wo transpose)
        cudaStreamWaitEvent(0, evZR[l], 0);
        cudaStreamWaitEvent(0, evL[l], 0);
        EpiArgs ea1 = {x, qkvzr, xin};
        gemm_f16_kernel<<<gO, 256, GEMM_SMEM>>>(
            y, wto + (size_t)l * dsz, bo + l * DD, nullptr,
            DD, DD, 2, 0, ea1);

        layernorm_warp_kernel<__half><<<lnBlocks, 256>>>(x, ln2w + l * DD, ln2b + l * DD, xn);
        gemm_f16_kernel<<<gM1, 256, GEMM_SMEM>>>(
            xn, wt1 + (size_t)l * DF * DD, b1 + l * DF, h1,
            DD, DF, 1, 1, eaNone);

        // W2 GEMM + fused gate2 (z recomputed from qkvzr logits)
        EpiArgs ea2 = {x, qkvzr, seq};
        gemm_f16_kernel<<<gO, 256, GEMM_SMEM>>>(
            h1, wt2 + (size_t)l * DD * DF, b2 + l * DD, nullptr,
            DF, DD, 3, 0, ea2);
    }

    layernorm_warp_kernel<float><<<lnBlocks, 256>>>(x, lnfw, lnfb, (float*)d_out);
}

// round 17
// speedup vs baseline: 1.0245x; 1.0245x over previous
#include <cuda_runtime.h>
#include <cuda_fp16.h>
#include <math.h>
#include <stdint.h>

// ---------------- problem constants ----------------
#define BB 2
#define TT 2048
#define DD 1024
#define HH 16
#define HD 64
#define NL 6
#define DF 4096
#define NTOK (BB*TT)          // 4096 rows
#define QKVLD 5120            // fused QKVZR row stride
#define EPSLN 1e-5f

// ---------------- device scratch (no allocs allowed) ----------------
__device__ float  g_x   [NTOK*DD];
__device__ __half g_xn  [NTOK*DD];
__device__ __half g_qkvzr[(size_t)NTOK*QKVLD];
__device__ __half g_y   [NTOK*DD];
__device__ __half g_zs  [NTOK*DD];
__device__ __half g_h1  [(size_t)NTOK*DF];

// transposed fp16 weights, K-major [N][K]
__device__ __half g_wtqkvzr[(size_t)NL*QKVLD*DD];
__device__ __half g_wto    [(size_t)NL*DD*DD];
__device__ __half g_wt1    [(size_t)NL*DF*DD];
__device__ __half g_wt2    [(size_t)NL*DD*DF];
__device__ float  g_bcat   [NL*QKVLD];

// ---------------- helpers ----------------
__device__ __forceinline__ float exp2a(float x) {
    float y;
    asm("ex2.approx.f32 %0, %1;" : "=f"(y) : "f"(x));
    return y;
}

__device__ __forceinline__ uint32_t half2_as_u(__half2 h) {
    return *reinterpret_cast<uint32_t*>(&h);
}

__device__ __forceinline__ void mma_f16(float* d, const uint32_t* a, const uint32_t* b) {
    asm volatile(
        "mma.sync.aligned.m16n8k16.row.col.f32.f16.f16.f32 "
        "{%0,%1,%2,%3}, {%4,%5,%6,%7}, {%8,%9}, {%0,%1,%2,%3};"
        : "+f"(d[0]), "+f"(d[1]), "+f"(d[2]), "+f"(d[3])
        : "r"(a[0]), "r"(a[1]), "r"(a[2]), "r"(a[3]),
          "r"(b[0]), "r"(b[1]));
}

#define LDSM4(r0, r1, r2, r3, addr) \
    asm volatile("ldmatrix.sync.aligned.m8n8.x4.shared.b16 {%0,%1,%2,%3}, [%4];" \
                 : "=r"(r0), "=r"(r1), "=r"(r2), "=r"(r3) : "r"(addr))

#define LDSM4T(r0, r1, r2, r3, addr) \
    asm volatile("ldmatrix.sync.aligned.m8n8.x4.trans.shared.b16 {%0,%1,%2,%3}, [%4];" \
                 : "=r"(r0), "=r"(r1), "=r"(r2), "=r"(r3) : "r"(addr))

__device__ __forceinline__ float sigmoidf_(float x) { return 1.0f / (1.0f + expf(-x)); }

__device__ __forceinline__ uint32_t smem_u32(const void* p) {
    uint32_t a;
    asm("{ .reg .u64 t; cvta.to.shared.u64 t, %1; cvt.u32.u64 %0, t; }" : "=r"(a) : "l"(p));
    return a;
}

__device__ __forceinline__ void cp16(uint32_t dst, const void* src) {
    asm volatile("cp.async.cg.shared.global [%0], [%1], 16;" :: "r"(dst), "l"(src) : "memory");
}
#define CP_COMMIT() asm volatile("cp.async.commit_group;" ::: "memory")
#define CP_WAIT(n)  asm volatile("cp.async.wait_group %0;" :: "n"(n) : "memory")

// ---------------- layernorm: one WARP per row, register-resident ----------------
template <typename OutT>
__global__ __launch_bounds__(256) void layernorm_warp_kernel(
        const float* __restrict__ x, const float* __restrict__ w,
        const float* __restrict__ b, OutT* __restrict__ out) {
    const int row  = blockIdx.x * 8 + (threadIdx.x >> 5);
    const int lane = threadIdx.x & 31;
    const float4* xr = (const float4*)(x + (size_t)row * DD);
    const float4* w4 = (const float4*)w;
    const float4* b4 = (const float4*)b;

    float4 v[8];
    float sum = 0.f, ss = 0.f;
    #pragma unroll
    for (int i = 0; i < 8; i++) {
        v[i] = xr[lane + 32 * i];
        sum += v[i].x + v[i].y + v[i].z + v[i].w;
        ss  += v[i].x * v[i].x + v[i].y * v[i].y + v[i].z * v[i].z + v[i].w * v[i].w;
    }
    #pragma unroll
    for (int d = 16; d > 0; d >>= 1) {
        sum += __shfl_xor_sync(0xffffffffu, sum, d);
        ss  += __shfl_xor_sync(0xffffffffu, ss, d);
    }
    const float mu = sum * (1.0f / DD);
    const float var = ss * (1.0f / DD) - mu * mu;
    const float rs = rsqrtf(var + EPSLN);

    #pragma unroll
    for (int i = 0; i < 8; i++) {
        const int c4 = lane + 32 * i;
        float4 wv = w4[c4];
        float4 bv = b4[c4];
        float o0 = (v[i].x - mu) * rs * wv.x + bv.x;
        float o1 = (v[i].y - mu) * rs * wv.y + bv.y;
        float o2 = (v[i].z - mu) * rs * wv.z + bv.z;
        float o3 = (v[i].w - mu) * rs * wv.w + bv.w;
        if (sizeof(OutT) == 2) {
            __half2 h0 = __floats2half2_rn(o0, o1);
            __half2 h1 = __floats2half2_rn(o2, o3);
            uint2 pk = {half2_as_u(h0), half2_as_u(h1)};
            *(uint2*)((__half*)out + (size_t)row * DD + c4 * 4) = pk;
        } else {
            float4 o = {o0, o1, o2, o3};
            *(float4*)((float*)out + (size_t)row * DD + c4 * 4) = o;
        }
    }
}

// ---------------- weight transpose to fp16 (single matrix) ----------------
__global__ __launch_bounds__(256) void transpose_h_kernel(
        const float* __restrict__ src, __half* __restrict__ dst, int K, int N) {
    __shared__ float tile[32][33];
    int k0 = blockIdx.y * 32, n0 = blockIdx.x * 32;
    int tx = threadIdx.x & 31, ty = threadIdx.x >> 5;
    #pragma unroll
    for (int i = 0; i < 4; i++)
        tile[ty + i * 8][tx] = src[(size_t)(k0 + ty + i * 8) * N + n0 + tx];
    __syncthreads();
    #pragma unroll
    for (int i = 0; i < 4; i++)
        dst[(size_t)(n0 + ty + i * 8) * K + k0 + tx] = __float2half(tile[tx][ty + i * 8]);
}

__global__ void biaspack_kernel(const float* __restrict__ bq, const float* __restrict__ bk,
                                const float* __restrict__ bv, const float* __restrict__ bz,
                                const float* __restrict__ br, float* __restrict__ out) {
    int i = blockIdx.x * blockDim.x + threadIdx.x;
    if (i >= NL * QKVLD) return;
    int l = i / QKVLD, j = i % QKVLD;
    int m = j >> 10, c = j & 1023;
    const float* src = (m == 0) ? bq : (m == 1) ? bk : (m == 2) ? bv : (m == 3) ? bz : br;
    out[i] = src[l * 1024 + c];
}

// ---------------- fp16 tensor-core GEMM: BK=32, 4-stage cp.async, ldmatrix ----------------
// epi: 0=bias->out, 1=bias+GELU->out, 2=gate1(x,zs), 3=gate2(x)
#define GBM 128
#define GBN 128
#define GBK 32
#define GP 40
#define GTILE (GBM*GP)
#define GSTAGES 4
#define GEMM_SMEM (2*GSTAGES*GTILE*2)

struct EpiArgs {
    float* xbuf;            // gate modes: x written here
    __half* zsbuf;          // gate1: z out (fp16); gate2: z in
    const __half* qz;       // gate1: fused qkvzr (z/r logits)
    const float* srcp;      // gate1: residual-x read source; gate2: sequences
};

__global__ __launch_bounds__(256) void gemm_f16_kernel(
        const __half* __restrict__ A, const __half* __restrict__ WT,
        const float* __restrict__ bias, void* __restrict__ Cout,
        int K, int ldC, int epi, int outHalf, EpiArgs ea) {
    extern __shared__ char dynsm[];
    __half* As = (__half*)dynsm;
    __half* Bs = As + GSTAGES * GTILE;

    const int tid  = threadIdx.x;
    const int warp = tid >> 5;
    const int lane = tid & 31;
    const int g    = lane >> 2;
    const int tg   = lane & 3;
    const int row0 = blockIdx.y * GBM;
    const int col0 = blockIdx.x * GBN;
    const int wm   = (warp >> 2) * 64;
    const int wn   = (warp & 3) * 32;

    float acc[4][4][4];
    #pragma unroll
    for (int i = 0; i < 4; i++)
        #pragma unroll
        for (int j = 0; j < 4; j++)
            #pragma unroll
            for (int c = 0; c < 4; c++) acc[i][j][c] = 0.f;

    const __half* Ag = A  + (size_t)row0 * K;
    const __half* Bg = WT + (size_t)col0 * K;
    const uint32_t as_base = smem_u32(As);
    const uint32_t bs_base = smem_u32(Bs);

    const uint32_t a_lane = ((uint32_t)(wm + (lane & 15)) * GP + ((lane >> 4) << 3)) * 2;
    const int bsel = (lane >> 3) & 3;
    const uint32_t b_lane = ((uint32_t)(wn + ((bsel >> 1) << 3) + (lane & 7)) * GP
                            + ((bsel & 1) << 3)) * 2;

    auto issue = [&](int it, int buf) {
        const int k0 = it * GBK;
        uint32_t ad = as_base + buf * (GTILE * 2);
        uint32_t bd = bs_base + buf * (GTILE * 2);
        #pragma unroll
        for (int i = 0; i < 2; i++) {
            int idx = tid + i * 256;
            int r = idx >> 2, seg = (idx & 3) * 8;
            cp16(ad + (r * GP + seg) * 2, Ag + (size_t)r * K + k0 + seg);
            cp16(bd + (r * GP + seg) * 2, Bg + (size_t)r * K + k0 + seg);
        }
    };

    const int nit = K / GBK;
    issue(0, 0); CP_COMMIT();
    if (nit > 1) { issue(1, 1); CP_COMMIT(); }
    if (nit > 2) { issue(2, 2); CP_COMMIT(); }

    for (int it = 0; it < nit; it++) {
        const int buf = it & 3;
        const int pend = ((it + 2 < nit) ? 2 : (it + 1 < nit) ? 1 : 0);
        if (pend == 2) CP_WAIT(2);
        else if (pend == 1) CP_WAIT(1);
        else CP_WAIT(0);
        __syncthreads();
        if (it + 3 < nit) { issue(it + 3, (it + 3) & 3); CP_COMMIT(); }

        const uint32_t ab = as_base + buf * (GTILE * 2) + a_lane;
        const uint32_t bb = bs_base + buf * (GTILE * 2) + b_lane;
        #pragma unroll
        for (int ks = 0; ks < 2; ks++) {
            const uint32_t ko = ks * 32;
            uint32_t af[4][4], bf[4][2];
            #pragma unroll
            for (int fm = 0; fm < 4; fm++)
                LDSM4(af[fm][0], af[fm][1], af[fm][2], af[fm][3],
                      ab + fm * (16 * GP * 2) + ko);
            #pragma unroll
            for (int fnp = 0; fnp < 2; fnp++)
                LDSM4(bf[2 * fnp][0], bf[2 * fnp][1], bf[2 * fnp + 1][0], bf[2 * fnp + 1][1],
                      bb + fnp * (16 * GP * 2) + ko);
            #pragma unroll
            for (int fm = 0; fm < 4; fm++)
                #pragma unroll
                for (int fn = 0; fn < 4; fn++)
                    mma_f16(acc[fm][fn], af[fm], bf[fn]);
        }
    }

    // ---------------- epilogue ----------------
    #pragma unroll
    for (int fm = 0; fm < 4; fm++) {
        int r1 = row0 + wm + fm * 16 + g;
        #pragma unroll
        for (int fn = 0; fn < 4; fn++) {
            int cl = wn + fn * 8 + tg * 2;
            int cg0 = col0 + cl;
            float bz0 = bias[cg0];
            float bz1 = bias[cg0 + 1];
            float v00 = acc[fm][fn][0] + bz0;
            float v01 = acc[fm][fn][1] + bz1;
            float v10 = acc[fm][fn][2] + bz0;
            float v11 = acc[fm][fn][3] + bz1;

            if (epi == 0) {
                if (outHalf) {
                    __half* ch = (__half*)Cout;
                    *(__half2*)(ch + (size_t)r1 * ldC + cg0) = __floats2half2_rn(v00, v01);
                    *(__half2*)(ch + (size_t)(r1 + 8) * ldC + cg0) = __floats2half2_rn(v10, v11);
                } else {
                    float* cf = (float*)Cout;
                    float2 o0 = {v00, v01};
                    float2 o1 = {v10, v11};
                    *(float2*)(cf + (size_t)r1 * ldC + cg0) = o0;
                    *(float2*)(cf + (size_t)(r1 + 8) * ldC + cg0) = o1;
                }
            } else if (epi == 1) {
                v00 = 0.5f * v00 * (1.0f + erff(v00 * 0.70710678118654752440f));
                v01 = 0.5f * v01 * (1.0f + erff(v01 * 0.70710678118654752440f));
                v10 = 0.5f * v10 * (1.0f + erff(v10 * 0.70710678118654752440f));
                v11 = 0.5f * v11 * (1.0f + erff(v11 * 0.70710678118654752440f));
                __half* ch = (__half*)Cout;
                *(__half2*)(ch + (size_t)r1 * ldC + cg0) = __floats2half2_rn(v00, v01);
                *(__half2*)(ch + (size_t)(r1 + 8) * ldC + cg0) = __floats2half2_rn(v10, v11);
            } else if (epi == 2) {
                // gate1: x = (1-z)*xin + z*tanh(r*v); zs = z (fp16)
                #pragma unroll
                for (int h = 0; h < 2; h++) {
                    int rr = r1 + h * 8;
                    float va = h ? v10 : v00;
                    float vb = h ? v11 : v01;
                    size_t qb_ = (size_t)rr * QKVLD + cg0;
                    __half2 zl = *(const __half2*)(ea.qz + qb_ + 3072);
                    __half2 rl = *(const __half2*)(ea.qz + qb_ + 4096);
                    float2 zf = __half22float2(zl);
                    float2 rf = __half22float2(rl);
                    float z0 = sigmoidf_(zf.x);
                    float z1 = sigmoidf_(zf.y);
                    float rg0 = sigmoidf_(rf.x);
                    float rg1 = sigmoidf_(rf.y);
                    size_t xi = (size_t)rr * DD + cg0;
                    float2 xv = *(const float2*)(ea.srcp + xi);
                    float h0 = tanhf(rg0 * va);
                    float h1v = tanhf(rg1 * vb);
                    float2 xo = {(1.0f - z0) * xv.x + z0 * h0,
                                 (1.0f - z1) * xv.y + z1 * h1v};
                    *(float2*)(ea.xbuf + xi) = xo;
                    *(__half2*)(ea.zsbuf + xi) = __floats2half2_rn(z0, z1);
                }
            } else {
                // gate2: x = (1-z)*x + z*v + src   (z from fp16 zs)
                #pragma unroll
                for (int h = 0; h < 2; h++) {
                    int rr = r1 + h * 8;
                    float va = h ? v10 : v00;
                    float vb = h ? v11 : v01;
                    size_t xi = (size_t)rr * DD + cg0;
                    float2 xv = *(float2*)(ea.xbuf + xi);
                    __half2 zh = *(const __half2*)(ea.zsbuf + xi);
                    float2 zv = __half22float2(zh);
                    float2 sv = *(float2*)(ea.srcp + xi);
                    float2 xo = {(1.0f - zv.x) * xv.x + zv.x * va + sv.x,
                                 (1.0f - zv.y) * xv.y + zv.y * vb + sv.y};
                    *(float2*)(ea.xbuf + xi) = xo;
                }
            }
        }
    }
}

// ---------------- fused causal flash attention (fp16 MMA, reg-P, ldmatrix.trans V) ----------------
#define FBM 128
#define FBN 64
#define FP 72   // pitch in halves
#define FLASH_SMEM ((FBM*FP + 4*FBN*FP) * 2)   // Q + K[2] + V[2] = 55296 B

__global__ __launch_bounds__(256, 2) void flash_attn_kernel(
        const __half* __restrict__ QKV, __half* __restrict__ O) {
    extern __shared__ char dynsm[];
    __half* Qs = (__half*)dynsm;             // [128][FP]
    __half* Ks = Qs + FBM * FP;              // [2][64][FP]
    __half* Vs = Ks + 2 * FBN * FP;          // [2][64][FP] token-major

    const int tx = threadIdx.x;
    const int warp = tx >> 5;
    const int lane = tx & 31;
    const int g  = lane >> 2;
    const int tg = lane & 3;
    const int qb = gridDim.x - 1 - blockIdx.x;
    const int bh = blockIdx.y;
    const int bb = bh >> 4, hh = bh & 15;
    const int qbase = qb * FBM;

    const __half* qptr = QKV + (size_t)bb * TT * QKVLD + hh * HD;
    const __half* kptr = qptr + 1024;
    const __half* vptr = qptr + 2048;

    const uint32_t ks_base = smem_u32(Ks);
    const uint32_t vs_base = smem_u32(Vs);

    #pragma unroll
    for (int i = 0; i < 4; i++) {
        int idx = tx + i * 256;
        int r = idx >> 3, c8 = (idx & 7) * 8;
        *(uint4*)&Qs[r * FP + c8] =
            *(const uint4*)(qptr + (size_t)(qbase + r) * QKVLD + c8);
    }

    float m0 = -1e30f, m1 = -1e30f, l0 = 0.f, l1 = 0.f;
    float o[8][4];
    #pragma unroll
    for (int nt = 0; nt < 8; nt++)
        #pragma unroll
        for (int c = 0; c < 4; c++) o[nt][c] = 0.f;

    const int myrow0 = qbase + warp * 16;
    const float sl2e = 0.125f * 1.44269504088896f;

    auto issueKV = [&](int kb, int buf) {
        #pragma unroll
        for (int i = 0; i < 2; i++) {
            int idx = tx + i * 256;
            int r = idx >> 3, c8 = (idx & 7) * 8;
            size_t gro = (size_t)(kb * FBN + r) * QKVLD + c8;
            uint32_t so = (uint32_t)(buf * (FBN * FP) + r * FP + c8) * 2;
            cp16(ks_base + so, kptr + gro);
            cp16(vs_base + so, vptr + gro);
        }
    };

    const uint32_t vt_lane = (uint32_t)((((lane >> 3) & 1) << 3) + (lane & 7)) * FP
                             + ((lane >> 4) << 3);

    const int kbmax = 2 * qb + 1;
    issueKV(0, 0); CP_COMMIT();

    for (int kb = 0; kb <= kbmax; kb++) {
        const int buf = kb & 1;
        if (kb < kbmax) { issueKV(kb + 1, buf ^ 1); CP_COMMIT(); CP_WAIT(1); }
        else            { CP_WAIT(0); }
        __syncthreads();

        if (kb * FBN <= myrow0 + 15) {
            const __half* Kb = Ks + buf * (FBN * FP);

            float s[8][4];
            #pragma unroll
            for (int nt = 0; nt < 8; nt++)
                #pragma unroll
                for (int c = 0; c < 4; c++) s[nt][c] = 0.f;

            #pragma unroll
            for (int ks = 0; ks < 4; ks++) {
                const int kc = ks * 16;
                uint32_t a[4];
                const __half* p = &Qs[(warp * 16 + g) * FP + kc + 2 * tg];
                a[0] = *(const uint32_t*)p;
                a[1] = *(const uint32_t*)(p + 8 * FP);
                a[2] = *(const uint32_t*)(p + 8);
                a[3] = *(const uint32_t*)(p + 8 * FP + 8);
                #pragma unroll
                for (int nt = 0; nt < 8; nt++) {
                    uint32_t b[2];
                    const __half* q = &Kb[(nt * 8 + g) * FP + kc + 2 * tg];
                    b[0] = *(const uint32_t*)q;
                    b[1] = *(const uint32_t*)(q + 8);
                    mma_f16(s[nt], a, b);
                }
            }

            const int r0 = myrow0 + g, r1 = r0 + 8;
            const bool dm = (kb >= 2 * qb);
            #pragma unroll
            for (int nt = 0; nt < 8; nt++) {
                int c0 = kb * FBN + nt * 8 + 2 * tg;
                s[nt][0] *= sl2e; s[nt][1] *= sl2e;
                s[nt][2] *= sl2e; s[nt][3] *= sl2e;
                if (dm) {
                    if (c0     > r0) s[nt][0] = -1e30f;
                    if (c0 + 1 > r0) s[nt][1] = -1e30f;
                    if (c0     > r1) s[nt][2] = -1e30f;
                    if (c0 + 1 > r1) s[nt][3] = -1e30f;
                }
            }

            float rm0 = -1e30f, rm1 = -1e30f;
            #pragma unroll
            for (int nt = 0; nt < 8; nt++) {
                rm0 = fmaxf(rm0, fmaxf(s[nt][0], s[nt][1]));
                rm1 = fmaxf(rm1, fmaxf(s[nt][2], s[nt][3]));
            }
            rm0 = fmaxf(rm0, __shfl_xor_sync(0xffffffffu, rm0, 1));
            rm0 = fmaxf(rm0, __shfl_xor_sync(0xffffffffu, rm0, 2));
            rm1 = fmaxf(rm1, __shfl_xor_sync(0xffffffffu, rm1, 1));
            rm1 = fmaxf(rm1, __shfl_xor_sync(0xffffffffu, rm1, 2));
            float mn0 = fmaxf(m0, rm0), mn1 = fmaxf(m1, rm1);
            float al0 = exp2a(m0 - mn0), al1 = exp2a(m1 - mn1);
            m0 = mn0; m1 = mn1;

            uint32_t pa[8][2];
            float rs0 = 0.f, rs1 = 0.f;
            #pragma unroll
            for (int nt = 0; nt < 8; nt++) {
                float p0 = exp2a(s[nt][0] - m0);
                float p1 = exp2a(s[nt][1] - m0);
                float p2 = exp2a(s[nt][2] - m1);
                float p3 = exp2a(s[nt][3] - m1);
                rs0 += p0 + p1;
                rs1 += p2 + p3;
                pa[nt][0] = half2_as_u(__floats2half2_rn(p0, p1));
                pa[nt][1] = half2_as_u(__floats2half2_rn(p2, p3));
            }
            rs0 += __shfl_xor_sync(0xffffffffu, rs0, 1);
            rs0 += __shfl_xor_sync(0xffffffffu, rs0, 2);
            rs1 += __shfl_xor_sync(0xffffffffu, rs1, 1);
            rs1 += __shfl_xor_sync(0xffffffffu, rs1, 2);
            l0 = l0 * al0 + rs0;
            l1 = l1 * al1 + rs1;
            #pragma unroll
            for (int nt = 0; nt < 8; nt++) {
                o[nt][0] *= al0; o[nt][1] *= al0;
                o[nt][2] *= al1; o[nt][3] *= al1;
            }

            const uint32_t vb_base = vs_base + (uint32_t)(buf * (FBN * FP) + vt_lane) * 2;
            #pragma unroll
            for (int j = 0; j < 4; j++) {
                uint32_t a[4] = {pa[2 * j][0], pa[2 * j][1],
                                 pa[2 * j + 1][0], pa[2 * j + 1][1]};
                #pragma unroll
                for (int ntp = 0; ntp < 4; ntp++) {
                    uint32_t b0, b1, b2, b3;
                    LDSM4T(b0, b1, b2, b3,
                           vb_base + (uint32_t)(j * 16 * FP + ntp * 16) * 2);
                    uint32_t bA[2] = {b0, b1};
                    uint32_t bB[2] = {b2, b3};
                    mma_f16(o[2 * ntp], a, bA);
                    mma_f16(o[2 * ntp + 1], a, bB);
                }
            }
        }
        __syncthreads();
    }

    float i0 = 1.0f / l0, i1 = 1.0f / l1;
    __half* ob = O + ((size_t)bb * TT + myrow0 + g) * DD + hh * HD;
    #pragma unroll
    for (int nt = 0; nt < 8; nt++) {
        int c = nt * 8 + 2 * tg;
        *(__half2*)(ob + c) = __floats2half2_rn(o[nt][0] * i0, o[nt][1] * i0);
        *(__half2*)(ob + (size_t)8 * DD + c) = __floats2half2_rn(o[nt][2] * i1, o[nt][3] * i1);
    }
}

// ---------------- host orchestration ----------------
static void* symv(const void* s) {
    void* p = nullptr;
    cudaGetSymbolAddress(&p, s);
    return p;
}

extern "C" void kernel_launch(void* const* d_in, const int* in_sizes, int n_in,
                              void* d_out, int out_size) {
    const float* seq  = (const float*)d_in[0];
    const float* Wq   = (const float*)d_in[1];
    const float* bq   = (const float*)d_in[2];
    const float* Wk   = (const float*)d_in[3];
    const float* bk   = (const float*)d_in[4];
    const float* Wv   = (const float*)d_in[5];
    const float* bv   = (const float*)d_in[6];
    const float* Wo   = (const float*)d_in[7];
    const float* bo   = (const float*)d_in[8];
    const float* Wz   = (const float*)d_in[9];
    const float* bz   = (const float*)d_in[10];
    const float* Wr   = (const float*)d_in[11];
    const float* br   = (const float*)d_in[12];
    const float* W1   = (const float*)d_in[13];
    const float* b1   = (const float*)d_in[14];
    const float* W2   = (const float*)d_in[15];
    const float* b2   = (const float*)d_in[16];
    const float* ln1w = (const float*)d_in[17];
    const float* ln1b = (const float*)d_in[18];
    const float* ln2w = (const float*)d_in[19];
    const float* ln2b = (const float*)d_in[20];
    const float* lnfw = (const float*)d_in[21];
    const float* lnfb = (const float*)d_in[22];

    float*  x     = (float*)symv(g_x);
    __half* xn    = (__half*)symv(g_xn);
    __half* qkvzr = (__half*)symv(g_qkvzr);
    __half* y     = (__half*)symv(g_y);
    __half* zs    = (__half*)symv(g_zs);
    __half* h1    = (__half*)symv(g_h1);
    __half* wtqkv = (__half*)symv(g_wtqkvzr);
    __half* wto   = (__half*)symv(g_wto);
    __half* wt1   = (__half*)symv(g_wt1);
    __half* wt2   = (__half*)symv(g_wt2);
    float*  bcat  = (float*)symv(g_bcat);

    static bool init_done = false;
    static cudaStream_t s2, s3;
    static cudaEvent_t evRoot, evW5[NL], evL[NL], evLN1[NL], evZR[NL];
    if (!init_done) {
        cudaFuncSetAttribute(flash_attn_kernel,
                             cudaFuncAttributeMaxDynamicSharedMemorySize, FLASH_SMEM);
        cudaFuncSetAttribute(gemm_f16_kernel,
                             cudaFuncAttributeMaxDynamicSharedMemorySize, GEMM_SMEM);
        cudaStreamCreateWithFlags(&s2, cudaStreamNonBlocking);
        cudaStreamCreateWithFlags(&s3, cudaStreamNonBlocking);
        cudaEventCreateWithFlags(&evRoot, cudaEventDisableTiming);
        for (int l = 0; l < NL; l++) {
            cudaEventCreateWithFlags(&evW5[l], cudaEventDisableTiming);
            cudaEventCreateWithFlags(&evL[l], cudaEventDisableTiming);
            cudaEventCreateWithFlags(&evLN1[l], cudaEventDisableTiming);
            cudaEventCreateWithFlags(&evZR[l], cudaEventDisableTiming);
        }
        init_done = true;
    }

    // ---- fork transposes onto s2 (R14 event topology); biaspack on main ----
    cudaEventRecord(evRoot, 0);
    cudaStreamWaitEvent(s2, evRoot, 0);
    {
        size_t dsz = (size_t)DD * DD;
        dim3 tD(DD / 32, DD / 32);
        dim3 t1(DF / 32, DD / 32);
        dim3 t2(DD / 32, DF / 32);
        for (int l = 0; l < NL; l++) {
            size_t o5 = (size_t)l * QKVLD * DD;
            transpose_h_kernel<<<tD, 256, 0, s2>>>(Wq + l * dsz, wtqkv + o5 + 0ull * dsz, DD, DD);
            transpose_h_kernel<<<tD, 256, 0, s2>>>(Wk + l * dsz, wtqkv + o5 + 1ull * dsz, DD, DD);
            transpose_h_kernel<<<tD, 256, 0, s2>>>(Wv + l * dsz, wtqkv + o5 + 2ull * dsz, DD, DD);
            transpose_h_kernel<<<tD, 256, 0, s2>>>(Wz + l * dsz, wtqkv + o5 + 3ull * dsz, DD, DD);
            transpose_h_kernel<<<tD, 256, 0, s2>>>(Wr + l * dsz, wtqkv + o5 + 4ull * dsz, DD, DD);
            cudaEventRecord(evW5[l], s2);
            transpose_h_kernel<<<tD, 256, 0, s2>>>(Wo + l * dsz, wto + l * dsz, DD, DD);
            transpose_h_kernel<<<t1, 256, 0, s2>>>(W1 + (size_t)l * DD * DF, wt1 + (size_t)l * DF * DD, DD, DF);
            transpose_h_kernel<<<t2, 256, 0, s2>>>(W2 + (size_t)l * DF * DD, wt2 + (size_t)l * DD * DF, DF, DD);
            cudaEventRecord(evL[l], s2);
        }
    }
    biaspack_kernel<<<(NL * QKVLD + 255) / 256, 256>>>(bq, bk, bv, bz, br, bcat);

    dim3 gQKV(3072 / GBN, NTOK / GBM);     // (24, 32)
    dim3 gZR(2048 / GBN, NTOK / GBM);      // (16, 32)
    dim3 gO(DD / GBN, NTOK / GBM);         // (8, 32)
    dim3 gM1(DF / GBN, NTOK / GBM);        // (32, 32)
    dim3 gFA(TT / FBM, BB * HH);           // (16, 32)
    const int lnBlocks = NTOK / 8;         // 512

    EpiArgs eaNone = {nullptr, nullptr, nullptr, nullptr};
    const size_t dsz = (size_t)DD * DD;

    for (int l = 0; l < NL; l++) {
        const float* xin = (l == 0) ? seq : x;
        const __half* wl = wtqkv + (size_t)l * QKVLD * DD;

        layernorm_warp_kernel<__half><<<lnBlocks, 256>>>(xin, ln1w + l * DD, ln1b + l * DD, xn);
        cudaEventRecord(evLN1[l], 0);

        // ZR projection on s3 (overlaps flash on main stream)
        cudaStreamWaitEvent(s3, evLN1[l], 0);
        cudaStreamWaitEvent(s3, evW5[l], 0);
        gemm_f16_kernel<<<gZR, 256, GEMM_SMEM, s3>>>(
            xn, wl + 3ull * dsz, bcat + l * QKVLD + 3072, qkvzr + 3072,
            DD, QKVLD, 0, 1, eaNone);
        cudaEventRecord(evZR[l], s3);

        // QKV projection on main stream
        cudaStreamWaitEvent(0, evW5[l], 0);
        gemm_f16_kernel<<<gQKV, 256, GEMM_SMEM>>>(
            xn, wl, bcat + l * QKVLD, qkvzr,
            DD, QKVLD, 0, 1, eaNone);

        flash_attn_kernel<<<gFA, 256, FLASH_SMEM>>>(qkvzr, y);

        // Wo GEMM + fused gate1 (needs z/r from s3 and Wo transpose)
        cudaStreamWaitEvent(0, evZR[l], 0);
        cudaStreamWaitEvent(0, evL[l], 0);
        EpiArgs ea1 = {x, zs, qkvzr, xin};
        gemm_f16_kernel<<<gO, 256, GEMM_SMEM>>>(
            y, wto + (size_t)l * dsz, bo + l * DD, nullptr,
            DD, DD, 2, 0, ea1);

        layernorm_warp_kernel<__half><<<lnBlocks, 256>>>(x, ln2w + l * DD, ln2b + l * DD, xn);
        gemm_f16_kernel<<<gM1, 256, GEMM_SMEM>>>(
            xn, wt1 + (size_t)l * DF * DD, b1 + l * DF, h1,
            DD, DF, 1, 1, eaNone);

        // W2 GEMM + fused gate2
        EpiArgs ea2 = {x, zs, nullptr, seq};
        gemm_f16_kernel<<<gO, 256, GEMM_SMEM>>>(
            h1, wt2 + (size_t)l * DD * DF, b2 + l * DD, nullptr,
            DF, DD, 3, 0, ea2);
    }

    layernorm_warp_kernel<float><<<lnBlocks, 256>>>(x, lnfw, lnfb, (float*)d_out);
}